// round 16
// baseline (speedup 1.0000x reference)
#include <cuda_runtime.h>
#include <cuda_bf16.h>
#include <math.h>
#include <stdint.h>

#define CC 256
#define BB 512
#define LL 256
#define RR 8
#define NG 1024

__device__ __align__(128) __nv_bfloat16 g_q_hi[BB * 512],  g_q_lo[BB * 512];
__device__ __align__(128) __nv_bfloat16 g_hb_hi[BB * 256], g_hb_lo[BB * 256];
__device__ __align__(128) __nv_bfloat16 g_rb_hi[BB * 256], g_rb_lo[BB * 256];
__device__ __align__(128) __nv_bfloat16 g_Wq_hi[NG * 512],  g_Wq_lo[NG * 512];
__device__ __align__(128) __nv_bfloat16 g_Wh0_hi[NG * 256], g_Wh0_lo[NG * 256];
__device__ __align__(128) __nv_bfloat16 g_Wh_hi[NG * 256],  g_Wh_lo[NG * 256];
__device__ __align__(128) __nv_bfloat16 g_Wr_hi[NG * 256],  g_Wr_lo[NG * 256];
__device__ __align__(128) float g_part0[BB * NG], g_part1[BB * NG], g_part2[BB * NG];
__device__ __align__(128) float g_hf[BB * CC];
__device__ __align__(128) float g_c[BB * CC];

__device__ __forceinline__ uint32_t smem_u32(const void* p) {
    uint32_t a;
    asm("{ .reg .u64 t; cvta.to.shared.u64 t, %1; cvt.u32.u64 %0, t; }" : "=r"(a) : "l"(p));
    return a;
}

#define CP16(dst, src) \
    asm volatile("cp.async.cg.shared.global [%0], [%1], 16;\n" :: "r"(dst), "l"(src))
#define CP_COMMIT() asm volatile("cp.async.commit_group;\n" ::: "memory")
#define CP_WAIT2()  asm volatile("cp.async.wait_group 2;\n" ::: "memory")
#define CP_WAIT1()  asm volatile("cp.async.wait_group 1;\n" ::: "memory")
#define CP_WAIT0()  asm volatile("cp.async.wait_group 0;\n" ::: "memory")

__device__ __forceinline__ void ldsm4(uint32_t* r, uint32_t addr) {
    asm volatile("ldmatrix.sync.aligned.m8n8.x4.shared.b16 {%0,%1,%2,%3}, [%4];"
                 : "=r"(r[0]), "=r"(r[1]), "=r"(r[2]), "=r"(r[3]) : "r"(addr));
}

__device__ __forceinline__ void mma16816(float* c, const uint32_t* a, const uint32_t* b) {
    asm volatile(
        "mma.sync.aligned.m16n8k16.row.col.f32.bf16.bf16.f32 "
        "{%0,%1,%2,%3}, {%4,%5,%6,%7}, {%8,%9}, {%0,%1,%2,%3};"
        : "+f"(c[0]), "+f"(c[1]), "+f"(c[2]), "+f"(c[3])
        : "r"(a[0]), "r"(a[1]), "r"(a[2]), "r"(a[3]), "r"(b[0]), "r"(b[1]));
}

__device__ __forceinline__ void split_bf16(float v, __nv_bfloat16& hi, __nv_bfloat16& lo) {
    hi = __float2bfloat16(v);
    lo = __float2bfloat16(v - __bfloat162float(hi));
}
__device__ __forceinline__ float sigf(float v) { return 1.f / (1.f + expf(-v)); }

__global__ void conv_all_kernel(const float* __restrict__ w_ih,
                                const float* __restrict__ w_hh) {
    int i = blockIdx.x * 256 + threadIdx.x;
    int n = i / 1280, c = i - n * 1280;
    __nv_bfloat16 hi, lo;
    if (c < 512) {
        split_bf16(w_ih[n * 512 + c], hi, lo);
        g_Wq_hi[n * 512 + c] = hi;  g_Wq_lo[n * 512 + c] = lo;
    } else if (c < 768) {
        int cc = c - 512;
        split_bf16(w_hh[n * 256 + cc], hi, lo);
        g_Wh0_hi[n * 256 + cc] = hi;  g_Wh0_lo[n * 256 + cc] = lo;
    } else if (c < 1024) {
        int cc = c - 768;
        split_bf16(w_ih[n * 512 + cc] + w_hh[n * 256 + cc], hi, lo);
        g_Wh_hi[n * 256 + cc] = hi;  g_Wh_lo[n * 256 + cc] = lo;
    } else {
        int cc = c - 1024;
        split_bf16(w_ih[n * 512 + 256 + cc], hi, lo);
        g_Wr_hi[n * 256 + cc] = hi;  g_Wr_lo[n * 256 + cc] = lo;
    }
}

__global__ void qconv_kernel(const float* __restrict__ q_star) {
    int i = blockIdx.x * 256 + threadIdx.x;
    __nv_bfloat16 hi, lo;
    split_bf16(q_star[i], hi, lo);
    g_q_hi[i] = hi;
    g_q_lo[i] = lo;
}

#define RSTRIDE 112
#define MATB 7168
#define BUFB (4 * MATB)
#define GEMM_SMEM (2 * BUFB)   // 57344

template <int NC, int AS, int WS>
__device__ __forceinline__ void gemm_body(
    const __nv_bfloat16* __restrict__ Ah, const __nv_bfloat16* __restrict__ Al,
    const __nv_bfloat16* __restrict__ Wh, const __nv_bfloat16* __restrict__ Wl,
    float* __restrict__ gp, char* smem, int tid, int m0, int n0, int kbase)
{
    const uint32_t sb = smem_u32(smem);
    const int lane = tid & 31, wid = tid >> 5;
    const int wm = wid >> 2, wn = wid & 3;

    float acc[2][2][4];
#pragma unroll
    for (int i = 0; i < 2; i++)
#pragma unroll
        for (int j = 0; j < 2; j++)
#pragma unroll
            for (int k = 0; k < 4; k++) acc[i][j][k] = 0.f;

    // Full coverage: 256 units of 16B per matrix (64 rows x 4 units).
    // Threads <128 copy the A pair; threads >=128 the W pair; 2 reps each.
    auto cp_chunk = [&](int c) {
        const int k0 = kbase + c * 32;
        const uint32_t bo = sb + (c & 1) * BUFB;
        int w = tid & 127;
#pragma unroll
        for (int rep = 0; rep < 2; rep++) {
            int u = w + rep * 128;          // 0..255
            int row = u >> 2, cu = u & 3;   // 64 rows x 4 x 16B
            uint32_t doff = bo + row * RSTRIDE + cu * 16;
            if (tid < 128) {
                size_t off = (size_t)(m0 + row) * AS + k0 + cu * 8;
                CP16(doff + 0 * MATB, Ah + off);
                CP16(doff + 1 * MATB, Al + off);
            } else {
                size_t off = (size_t)(n0 + row) * WS + k0 + cu * 8;
                CP16(doff + 2 * MATB, Wh + off);
                CP16(doff + 3 * MATB, Wl + off);
            }
        }
    };

    cp_chunk(0);
    CP_COMMIT();

    const int a_row = (lane & 15);
    const int a_kb  = (lane >> 4) * 16;
    const int b_row = (lane & 7) + ((lane >> 4) << 3);
    const int b_kb  = ((lane >> 3) & 1) * 16;

    for (int c = 0; c < NC; c++) {
        if (c + 1 < NC) {
            cp_chunk(c + 1);
            CP_COMMIT();
            CP_WAIT1();
        } else {
            CP_WAIT0();
        }
        __syncthreads();

        const uint32_t bo = sb + (c & 1) * BUFB;
#pragma unroll
        for (int s = 0; s < 2; s++) {
            const int kb = s * 32;
            uint32_t ah[2][4], al[2][4], bh[4], bl[4];
#pragma unroll
            for (int mt = 0; mt < 2; mt++) {
                uint32_t ra = (wm * 32 + mt * 16 + a_row) * RSTRIDE + kb + a_kb;
                ldsm4(ah[mt], bo + 0 * MATB + ra);
                ldsm4(al[mt], bo + 1 * MATB + ra);
            }
            {
                uint32_t rb = (wn * 16 + b_row) * RSTRIDE + kb + b_kb;
                ldsm4(bh, bo + 2 * MATB + rb);
                ldsm4(bl, bo + 3 * MATB + rb);
            }
#pragma unroll
            for (int mt = 0; mt < 2; mt++)
#pragma unroll
                for (int nf = 0; nf < 2; nf++)
                    mma16816(acc[mt][nf], ah[mt], &bh[nf * 2]);
#pragma unroll
            for (int mt = 0; mt < 2; mt++)
#pragma unroll
                for (int nf = 0; nf < 2; nf++)
                    mma16816(acc[mt][nf], ah[mt], &bl[nf * 2]);
#pragma unroll
            for (int mt = 0; mt < 2; mt++)
#pragma unroll
                for (int nf = 0; nf < 2; nf++)
                    mma16816(acc[mt][nf], al[mt], &bh[nf * 2]);
        }
        __syncthreads();
    }

    const int er = lane >> 2, ec = (lane & 3) * 2;
#pragma unroll
    for (int mt = 0; mt < 2; mt++) {
        int row = m0 + wm * 32 + mt * 16 + er;
#pragma unroll
        for (int nf = 0; nf < 2; nf++) {
            int col = n0 + wn * 16 + nf * 8 + ec;
            *(float2*)&gp[(size_t)row * NG + col] =
                make_float2(acc[mt][nf][0], acc[mt][nf][1]);
            *(float2*)&gp[(size_t)(row + 8) * NG + col] =
                make_float2(acc[mt][nf][2], acc[mt][nf][3]);
        }
    }
}

__device__ __forceinline__ void asit_role(const float* __restrict__ x,
                                          const float* __restrict__ bank_s,
                                          const int* __restrict__ index_p,
                                          char* smem) {
    float* xs = (float*)smem;
    __shared__ float s[LL];
    const int b = blockIdx.x, tid = threadIdx.x;
    int idx = *index_p;
    s[tid] = bank_s[((size_t)b * RR + idx) * LL + tid];

    const float* xb = x + (size_t)b * LL * CC;
    uint32_t sbx = smem_u32(xs);

    auto cp_chunk = [&](int ch) {
        const float* src = xb + (size_t)ch * 16 * CC;
        uint32_t dst = sbx + (ch % 3) * 16384;
#pragma unroll
        for (int i = 0; i < 4; i++)
            CP16(dst + (tid + i * 256) * 16, src + (tid + i * 256) * 4);
    };

    cp_chunk(0); CP_COMMIT();
    cp_chunk(1); CP_COMMIT();

    float acc = 0.f;
    for (int ch = 0; ch < 16; ch++) {
        if (ch + 2 < 16) {
            cp_chunk(ch + 2); CP_COMMIT(); CP_WAIT2();
        } else if (ch + 1 < 16) {
            CP_WAIT1();
        } else {
            CP_WAIT0();
        }
        __syncthreads();
        const float* cx = xs + (ch % 3) * 4096;
#pragma unroll
        for (int l = 0; l < 16; l++)
            acc = fmaf(s[ch * 16 + l], cx[l * CC + tid], acc);
        __syncthreads();
    }

    g_hf[b * CC + tid] = acc;
    g_c[b * CC + tid] = 0.f;
    __nv_bfloat16 hi, lo;
    split_bf16(acc, hi, lo);
    g_hb_hi[b * CC + tid] = hi;
    g_hb_lo[b * CC + tid] = lo;
}

__device__ __forceinline__ void attn_role(const float* __restrict__ x,
                                          float* __restrict__ out,
                                          char* smem) {
    float* xs = (float*)smem;
    __shared__ float ebuf[16], pbuf[16];
    const int b = blockIdx.x, tid = threadIdx.x;
    const int lane = tid & 31, w = tid >> 5;

    const float* q = g_hf + (size_t)b * CC;
    float qreg[8];
#pragma unroll
    for (int j = 0; j < 8; j++) qreg[j] = q[lane + 32 * j];

    float m = -INFINITY, ssum = 0.f, r = 0.f;
    const float* xb = x + (size_t)b * LL * CC;
    uint32_t sbx = smem_u32(xs);

    auto cp_chunk = [&](int ch) {
        const float* src = xb + (size_t)ch * 16 * CC;
        uint32_t dst = sbx + (ch % 3) * 16384;
#pragma unroll
        for (int i = 0; i < 4; i++)
            CP16(dst + (tid + i * 256) * 16, src + (tid + i * 256) * 4);
    };

    cp_chunk(0); CP_COMMIT();
    cp_chunk(1); CP_COMMIT();

    for (int ch = 0; ch < 16; ch++) {
        if (ch + 2 < 16) {
            cp_chunk(ch + 2); CP_COMMIT(); CP_WAIT2();
        } else if (ch + 1 < 16) {
            CP_WAIT1();
        } else {
            CP_WAIT0();
        }
        __syncthreads();
        const float* cx = xs + (ch % 3) * 4096;

#pragma unroll
        for (int jj = 0; jj < 2; jj++) {
            int l = w * 2 + jj;
            const float* row = cx + l * CC;
            float d = 0.f;
#pragma unroll
            for (int j = 0; j < 8; j++) d = fmaf(row[lane + 32 * j], qreg[j], d);
#pragma unroll
            for (int off = 16; off; off >>= 1) d += __shfl_xor_sync(0xffffffffu, d, off);
            if (lane == 0) ebuf[l] = d;
        }
        __syncthreads();

        float cm = ebuf[0];
#pragma unroll
        for (int l = 1; l < 16; l++) cm = fmaxf(cm, ebuf[l]);
        float nm = fmaxf(m, cm);
        if (tid < 16) pbuf[tid] = expf(ebuf[tid] - nm);
        float alpha = expf(m - nm);
        __syncthreads();

        r *= alpha; ssum *= alpha;
        float ps = 0.f;
#pragma unroll
        for (int l = 0; l < 16; l++) {
            float p = pbuf[l];
            r = fmaf(p, cx[l * CC + tid], r);
            ps += p;
        }
        ssum += ps;
        m = nm;
        __syncthreads();
    }

    float rr = r / (ssum + 1e-16f);
    out[(size_t)b * (2 * CC) + CC + tid] = rr;
    __nv_bfloat16 hi, lo;
    split_bf16(rr, hi, lo);
    g_rb_hi[b * CC + tid] = hi;
    g_rb_lo[b * CC + tid] = lo;
}

__global__ __launch_bounds__(256, 2)
void f0_kernel(const float* __restrict__ x, const float* __restrict__ bank_s,
               const int* __restrict__ index_p) {
    extern __shared__ char smem[];
    if (blockIdx.x < BB) {
        asit_role(x, bank_s, index_p, smem);
    } else {
        int bx = blockIdx.x - BB;
        gemm_body<16, 512, 512>(g_q_hi, g_q_lo, g_Wq_hi, g_Wq_lo,
                                g_part0, smem, threadIdx.x,
                                (bx >> 4) * 64, (bx & 15) * 64, 0);
    }
}

__global__ __launch_bounds__(256, 2)
void f1_kernel(const float* __restrict__ x, float* __restrict__ out) {
    extern __shared__ char smem[];
    if (blockIdx.x < BB) {
        attn_role(x, out, smem);
    } else {
        int bx = blockIdx.x - BB;
        gemm_body<8, 256, 256>(g_hb_hi, g_hb_lo, g_Wh_hi, g_Wh_lo,
                               g_part0, smem, threadIdx.x,
                               (bx >> 4) * 64, (bx & 15) * 64, 0);
    }
}

template <int SEL>
__global__ __launch_bounds__(256, 2)
void g_kernel() {
    extern __shared__ char smem[];
    int m0 = blockIdx.y * 64;
    int n0 = blockIdx.x * 64;
    int kbase = blockIdx.z * 128;
    float* gp = blockIdx.z ? g_part2 : g_part1;
    if (SEL == 0)
        gemm_body<4, 256, 256>(g_hb_hi, g_hb_lo, g_Wh0_hi, g_Wh0_lo,
                               gp, smem, threadIdx.x, m0, n0, kbase);
    else
        gemm_body<4, 256, 256>(g_rb_hi, g_rb_lo, g_Wr_hi, g_Wr_lo,
                               gp, smem, threadIdx.x, m0, n0, kbase);
}

__global__ void lstm_kernel(const float* __restrict__ b_ih,
                            const float* __restrict__ b_hh,
                            float* __restrict__ out) {
    int i = blockIdx.x * 256 + threadIdx.x;
    int b = i >> 8, ch = i & 255;
    size_t base = (size_t)b * NG;
    float ig = g_part0[base + ch]       + g_part1[base + ch]       + g_part2[base + ch]       + b_ih[ch]       + b_hh[ch];
    float fg = g_part0[base + 256 + ch] + g_part1[base + 256 + ch] + g_part2[base + 256 + ch] + b_ih[256 + ch] + b_hh[256 + ch];
    float gg = g_part0[base + 512 + ch] + g_part1[base + 512 + ch] + g_part2[base + 512 + ch] + b_ih[512 + ch] + b_hh[512 + ch];
    float og = g_part0[base + 768 + ch] + g_part1[base + 768 + ch] + g_part2[base + 768 + ch] + b_ih[768 + ch] + b_hh[768 + ch];
    float cc = sigf(fg) * g_c[i] + sigf(ig) * tanhf(gg);
    float h  = sigf(og) * tanhf(cc);
    g_c[i] = cc;
    g_hf[i] = h;
    out[(size_t)b * (2 * CC) + ch] = h;
    __nv_bfloat16 hi, lo;
    split_bf16(h, hi, lo);
    g_hb_hi[i] = hi;
    g_hb_lo[i] = lo;
}

extern "C" void kernel_launch(void* const* d_in, const int* in_sizes, int n_in,
                              void* d_out, int out_size) {
    const float* x      = (const float*)d_in[0];
    const float* q_star = (const float*)d_in[2];
    const float* bank_s = (const float*)d_in[3];
    const float* w_ih   = (const float*)d_in[4];
    const float* w_hh   = (const float*)d_in[5];
    const float* b_ih   = (const float*)d_in[6];
    const float* b_hh   = (const float*)d_in[7];
    const int*   index  = (const int*)d_in[8];
    float* out = (float*)d_out;

    cudaFuncSetAttribute(f0_kernel, cudaFuncAttributeMaxDynamicSharedMemorySize, GEMM_SMEM);
    cudaFuncSetAttribute(f1_kernel, cudaFuncAttributeMaxDynamicSharedMemorySize, GEMM_SMEM);
    cudaFuncSetAttribute(g_kernel<0>, cudaFuncAttributeMaxDynamicSharedMemorySize, GEMM_SMEM);
    cudaFuncSetAttribute(g_kernel<1>, cudaFuncAttributeMaxDynamicSharedMemorySize, GEMM_SMEM);

    conv_all_kernel<<<(NG * 1280) / 256, 256>>>(w_ih, w_hh);
    qconv_kernel<<<(BB * 512) / 256, 256>>>(q_star);

    // step 1: asit || q_star-GEMM(K=512)->part0 ; h0@w_hh(K=256,z2)->part1/2 ; lstm
    f0_kernel<<<BB + 128, 256, GEMM_SMEM>>>(x, bank_s, index);
    g_kernel<0><<<dim3(16, 8, 2), 256, GEMM_SMEM>>>();
    lstm_kernel<<<BB, 256>>>(b_ih, b_hh, out);

    // steps 2..3: attn || h@Wh(K=256)->part0 ; r@Wr(K=256,z2)->part1/2 ; lstm
    for (int t = 0; t < 2; t++) {
        f1_kernel<<<BB + 128, 256, GEMM_SMEM>>>(x, out);
        g_kernel<1><<<dim3(16, 8, 2), 256, GEMM_SMEM>>>();
        lstm_kernel<<<BB, 256>>>(b_ih, b_hh, out);
    }

    // final attention (attn blocks only)
    f1_kernel<<<BB, 256, GEMM_SMEM>>>(x, out);
}

// round 17
// speedup vs baseline: 1.0998x; 1.0998x over previous
#include <cuda_runtime.h>
#include <cuda_bf16.h>
#include <math.h>
#include <stdint.h>

#define CC 256
#define BB 512
#define LL 256
#define RR 8
#define NG 1024
#define NGEMM 128   // gemm-role blocks in fused kernels (scheduled FIRST)

__device__ __align__(128) __nv_bfloat16 g_q_hi[BB * 512],  g_q_lo[BB * 512];
__device__ __align__(128) __nv_bfloat16 g_hb_hi[BB * 256], g_hb_lo[BB * 256];
__device__ __align__(128) __nv_bfloat16 g_rb_hi[BB * 256], g_rb_lo[BB * 256];
__device__ __align__(128) __nv_bfloat16 g_Wq_hi[NG * 512],  g_Wq_lo[NG * 512];
__device__ __align__(128) __nv_bfloat16 g_Wh0_hi[NG * 256], g_Wh0_lo[NG * 256];
__device__ __align__(128) __nv_bfloat16 g_Wh_hi[NG * 256],  g_Wh_lo[NG * 256];
__device__ __align__(128) __nv_bfloat16 g_Wr_hi[NG * 256],  g_Wr_lo[NG * 256];
__device__ __align__(128) float g_part0[BB * NG], g_part1[BB * NG], g_part2[BB * NG];
__device__ __align__(128) float g_hf[BB * CC];
__device__ __align__(128) float g_c[BB * CC];

__device__ __forceinline__ uint32_t smem_u32(const void* p) {
    uint32_t a;
    asm("{ .reg .u64 t; cvta.to.shared.u64 t, %1; cvt.u32.u64 %0, t; }" : "=r"(a) : "l"(p));
    return a;
}

#define CP16(dst, src) \
    asm volatile("cp.async.cg.shared.global [%0], [%1], 16;\n" :: "r"(dst), "l"(src))
#define CP_COMMIT() asm volatile("cp.async.commit_group;\n" ::: "memory")
#define CP_WAIT2()  asm volatile("cp.async.wait_group 2;\n" ::: "memory")
#define CP_WAIT1()  asm volatile("cp.async.wait_group 1;\n" ::: "memory")
#define CP_WAIT0()  asm volatile("cp.async.wait_group 0;\n" ::: "memory")

__device__ __forceinline__ void ldsm4(uint32_t* r, uint32_t addr) {
    asm volatile("ldmatrix.sync.aligned.m8n8.x4.shared.b16 {%0,%1,%2,%3}, [%4];"
                 : "=r"(r[0]), "=r"(r[1]), "=r"(r[2]), "=r"(r[3]) : "r"(addr));
}

__device__ __forceinline__ void mma16816(float* c, const uint32_t* a, const uint32_t* b) {
    asm volatile(
        "mma.sync.aligned.m16n8k16.row.col.f32.bf16.bf16.f32 "
        "{%0,%1,%2,%3}, {%4,%5,%6,%7}, {%8,%9}, {%0,%1,%2,%3};"
        : "+f"(c[0]), "+f"(c[1]), "+f"(c[2]), "+f"(c[3])
        : "r"(a[0]), "r"(a[1]), "r"(a[2]), "r"(a[3]), "r"(b[0]), "r"(b[1]));
}

__device__ __forceinline__ void split_bf16(float v, __nv_bfloat16& hi, __nv_bfloat16& lo) {
    hi = __float2bfloat16(v);
    lo = __float2bfloat16(v - __bfloat162float(hi));
}
__device__ __forceinline__ float sigf(float v) { return 1.f / (1.f + expf(-v)); }

__global__ void conv_all_kernel(const float* __restrict__ w_ih,
                                const float* __restrict__ w_hh) {
    int i = blockIdx.x * 256 + threadIdx.x;
    int n = i / 1280, c = i - n * 1280;
    __nv_bfloat16 hi, lo;
    if (c < 512) {
        split_bf16(w_ih[n * 512 + c], hi, lo);
        g_Wq_hi[n * 512 + c] = hi;  g_Wq_lo[n * 512 + c] = lo;
    } else if (c < 768) {
        int cc = c - 512;
        split_bf16(w_hh[n * 256 + cc], hi, lo);
        g_Wh0_hi[n * 256 + cc] = hi;  g_Wh0_lo[n * 256 + cc] = lo;
    } else if (c < 1024) {
        int cc = c - 768;
        split_bf16(w_ih[n * 512 + cc] + w_hh[n * 256 + cc], hi, lo);
        g_Wh_hi[n * 256 + cc] = hi;  g_Wh_lo[n * 256 + cc] = lo;
    } else {
        int cc = c - 1024;
        split_bf16(w_ih[n * 512 + 256 + cc], hi, lo);
        g_Wr_hi[n * 256 + cc] = hi;  g_Wr_lo[n * 256 + cc] = lo;
    }
}

__global__ void qconv_kernel(const float* __restrict__ q_star) {
    int i = blockIdx.x * 256 + threadIdx.x;
    __nv_bfloat16 hi, lo;
    split_bf16(q_star[i], hi, lo);
    g_q_hi[i] = hi;
    g_q_lo[i] = lo;
}

#define RSTRIDE 112
#define MATB 7168
#define BUFB (4 * MATB)
#define GEMM_SMEM (2 * BUFB)   // 57344

template <int NC, int AS, int WS>
__device__ __forceinline__ void gemm_body(
    const __nv_bfloat16* __restrict__ Ah, const __nv_bfloat16* __restrict__ Al,
    const __nv_bfloat16* __restrict__ Wh, const __nv_bfloat16* __restrict__ Wl,
    float* __restrict__ gp, char* smem, int tid, int m0, int n0, int kbase)
{
    const uint32_t sb = smem_u32(smem);
    const int lane = tid & 31, wid = tid >> 5;
    const int wm = wid >> 2, wn = wid & 3;

    float acc[2][2][4];
#pragma unroll
    for (int i = 0; i < 2; i++)
#pragma unroll
        for (int j = 0; j < 2; j++)
#pragma unroll
            for (int k = 0; k < 4; k++) acc[i][j][k] = 0.f;

    // Full coverage: 256 units of 16B per matrix (64 rows x 4 units).
    auto cp_chunk = [&](int c) {
        const int k0 = kbase + c * 32;
        const uint32_t bo = sb + (c & 1) * BUFB;
        int w = tid & 127;
#pragma unroll
        for (int rep = 0; rep < 2; rep++) {
            int u = w + rep * 128;
            int row = u >> 2, cu = u & 3;
            uint32_t doff = bo + row * RSTRIDE + cu * 16;
            if (tid < 128) {
                size_t off = (size_t)(m0 + row) * AS + k0 + cu * 8;
                CP16(doff + 0 * MATB, Ah + off);
                CP16(doff + 1 * MATB, Al + off);
            } else {
                size_t off = (size_t)(n0 + row) * WS + k0 + cu * 8;
                CP16(doff + 2 * MATB, Wh + off);
                CP16(doff + 3 * MATB, Wl + off);
            }
        }
    };

    cp_chunk(0);
    CP_COMMIT();

    const int a_row = (lane & 15);
    const int a_kb  = (lane >> 4) * 16;
    const int b_row = (lane & 7) + ((lane >> 4) << 3);
    const int b_kb  = ((lane >> 3) & 1) * 16;

    for (int c = 0; c < NC; c++) {
        if (c + 1 < NC) {
            cp_chunk(c + 1);
            CP_COMMIT();
            CP_WAIT1();
        } else {
            CP_WAIT0();
        }
        __syncthreads();

        const uint32_t bo = sb + (c & 1) * BUFB;
#pragma unroll
        for (int s = 0; s < 2; s++) {
            const int kb = s * 32;
            uint32_t ah[2][4], al[2][4], bh[4], bl[4];
#pragma unroll
            for (int mt = 0; mt < 2; mt++) {
                uint32_t ra = (wm * 32 + mt * 16 + a_row) * RSTRIDE + kb + a_kb;
                ldsm4(ah[mt], bo + 0 * MATB + ra);
                ldsm4(al[mt], bo + 1 * MATB + ra);
            }
            {
                uint32_t rb = (wn * 16 + b_row) * RSTRIDE + kb + b_kb;
                ldsm4(bh, bo + 2 * MATB + rb);
                ldsm4(bl, bo + 3 * MATB + rb);
            }
#pragma unroll
            for (int mt = 0; mt < 2; mt++)
#pragma unroll
                for (int nf = 0; nf < 2; nf++)
                    mma16816(acc[mt][nf], ah[mt], &bh[nf * 2]);
#pragma unroll
            for (int mt = 0; mt < 2; mt++)
#pragma unroll
                for (int nf = 0; nf < 2; nf++)
                    mma16816(acc[mt][nf], ah[mt], &bl[nf * 2]);
#pragma unroll
            for (int mt = 0; mt < 2; mt++)
#pragma unroll
                for (int nf = 0; nf < 2; nf++)
                    mma16816(acc[mt][nf], al[mt], &bh[nf * 2]);
        }
        __syncthreads();
    }

    const int er = lane >> 2, ec = (lane & 3) * 2;
#pragma unroll
    for (int mt = 0; mt < 2; mt++) {
        int row = m0 + wm * 32 + mt * 16 + er;
#pragma unroll
        for (int nf = 0; nf < 2; nf++) {
            int col = n0 + wn * 16 + nf * 8 + ec;
            *(float2*)&gp[(size_t)row * NG + col] =
                make_float2(acc[mt][nf][0], acc[mt][nf][1]);
            *(float2*)&gp[(size_t)(row + 8) * NG + col] =
                make_float2(acc[mt][nf][2], acc[mt][nf][3]);
        }
    }
}

__device__ __forceinline__ void asit_role(const float* __restrict__ x,
                                          const float* __restrict__ bank_s,
                                          const int* __restrict__ index_p,
                                          char* smem, int b) {
    float* xs = (float*)smem;
    __shared__ float s[LL];
    const int tid = threadIdx.x;
    int idx = *index_p;
    s[tid] = bank_s[((size_t)b * RR + idx) * LL + tid];

    const float* xb = x + (size_t)b * LL * CC;
    uint32_t sbx = smem_u32(xs);

    auto cp_chunk = [&](int ch) {
        const float* src = xb + (size_t)ch * 16 * CC;
        uint32_t dst = sbx + (ch % 3) * 16384;
#pragma unroll
        for (int i = 0; i < 4; i++)
            CP16(dst + (tid + i * 256) * 16, src + (tid + i * 256) * 4);
    };

    cp_chunk(0); CP_COMMIT();
    cp_chunk(1); CP_COMMIT();

    float acc = 0.f;
    for (int ch = 0; ch < 16; ch++) {
        if (ch + 2 < 16) {
            cp_chunk(ch + 2); CP_COMMIT(); CP_WAIT2();
        } else if (ch + 1 < 16) {
            CP_WAIT1();
        } else {
            CP_WAIT0();
        }
        __syncthreads();
        const float* cx = xs + (ch % 3) * 4096;
#pragma unroll
        for (int l = 0; l < 16; l++)
            acc = fmaf(s[ch * 16 + l], cx[l * CC + tid], acc);
        __syncthreads();
    }

    g_hf[b * CC + tid] = acc;
    g_c[b * CC + tid] = 0.f;
    __nv_bfloat16 hi, lo;
    split_bf16(acc, hi, lo);
    g_hb_hi[b * CC + tid] = hi;
    g_hb_lo[b * CC + tid] = lo;
}

__device__ __forceinline__ void attn_role(const float* __restrict__ x,
                                          float* __restrict__ out,
                                          char* smem, int b) {
    float* xs = (float*)smem;
    __shared__ float ebuf[16], pbuf[16];
    const int tid = threadIdx.x;
    const int lane = tid & 31, w = tid >> 5;

    const float* q = g_hf + (size_t)b * CC;
    float qreg[8];
#pragma unroll
    for (int j = 0; j < 8; j++) qreg[j] = q[lane + 32 * j];

    float m = -INFINITY, ssum = 0.f, r = 0.f;
    const float* xb = x + (size_t)b * LL * CC;
    uint32_t sbx = smem_u32(xs);

    auto cp_chunk = [&](int ch) {
        const float* src = xb + (size_t)ch * 16 * CC;
        uint32_t dst = sbx + (ch % 3) * 16384;
#pragma unroll
        for (int i = 0; i < 4; i++)
            CP16(dst + (tid + i * 256) * 16, src + (tid + i * 256) * 4);
    };

    cp_chunk(0); CP_COMMIT();
    cp_chunk(1); CP_COMMIT();

    for (int ch = 0; ch < 16; ch++) {
        if (ch + 2 < 16) {
            cp_chunk(ch + 2); CP_COMMIT(); CP_WAIT2();
        } else if (ch + 1 < 16) {
            CP_WAIT1();
        } else {
            CP_WAIT0();
        }
        __syncthreads();
        const float* cx = xs + (ch % 3) * 4096;

#pragma unroll
        for (int jj = 0; jj < 2; jj++) {
            int l = w * 2 + jj;
            const float* row = cx + l * CC;
            float d = 0.f;
#pragma unroll
            for (int j = 0; j < 8; j++) d = fmaf(row[lane + 32 * j], qreg[j], d);
#pragma unroll
            for (int off = 16; off; off >>= 1) d += __shfl_xor_sync(0xffffffffu, d, off);
            if (lane == 0) ebuf[l] = d;
        }
        __syncthreads();

        float cm = ebuf[0];
#pragma unroll
        for (int l = 1; l < 16; l++) cm = fmaxf(cm, ebuf[l]);
        float nm = fmaxf(m, cm);
        if (tid < 16) pbuf[tid] = expf(ebuf[tid] - nm);
        float alpha = expf(m - nm);
        __syncthreads();

        r *= alpha; ssum *= alpha;
        float ps = 0.f;
#pragma unroll
        for (int l = 0; l < 16; l++) {
            float p = pbuf[l];
            r = fmaf(p, cx[l * CC + tid], r);
            ps += p;
        }
        ssum += ps;
        m = nm;
        __syncthreads();
    }

    float rr = r / (ssum + 1e-16f);
    out[(size_t)b * (2 * CC) + CC + tid] = rr;
    __nv_bfloat16 hi, lo;
    split_bf16(rr, hi, lo);
    g_rb_hi[b * CC + tid] = hi;
    g_rb_lo[b * CC + tid] = lo;
}

// GEMM blocks FIRST so they enter the first wave and overlap the memory role.
__global__ __launch_bounds__(256, 3)
void f0_kernel(const float* __restrict__ x, const float* __restrict__ bank_s,
               const int* __restrict__ index_p) {
    extern __shared__ char smem[];
    if (blockIdx.x < NGEMM) {
        int bx = blockIdx.x;
        gemm_body<16, 512, 512>(g_q_hi, g_q_lo, g_Wq_hi, g_Wq_lo,
                                g_part0, smem, threadIdx.x,
                                (bx >> 4) * 64, (bx & 15) * 64, 0);
    } else {
        asit_role(x, bank_s, index_p, smem, blockIdx.x - NGEMM);
    }
}

__global__ __launch_bounds__(256, 3)
void f1_kernel(const float* __restrict__ x, float* __restrict__ out, int ngemm) {
    extern __shared__ char smem[];
    if (blockIdx.x < (unsigned)ngemm) {
        int bx = blockIdx.x;
        gemm_body<8, 256, 256>(g_hb_hi, g_hb_lo, g_Wh_hi, g_Wh_lo,
                               g_part0, smem, threadIdx.x,
                               (bx >> 4) * 64, (bx & 15) * 64, 0);
    } else {
        attn_role(x, out, smem, blockIdx.x - ngemm);
    }
}

template <int SEL>
__global__ __launch_bounds__(256, 3)
void g_kernel() {
    extern __shared__ char smem[];
    int m0 = blockIdx.y * 64;
    int n0 = blockIdx.x * 64;
    int kbase = blockIdx.z * 128;
    float* gp = blockIdx.z ? g_part2 : g_part1;
    if (SEL == 0)
        gemm_body<4, 256, 256>(g_hb_hi, g_hb_lo, g_Wh0_hi, g_Wh0_lo,
                               gp, smem, threadIdx.x, m0, n0, kbase);
    else
        gemm_body<4, 256, 256>(g_rb_hi, g_rb_lo, g_Wr_hi, g_Wr_lo,
                               gp, smem, threadIdx.x, m0, n0, kbase);
}

__global__ void lstm_kernel(const float* __restrict__ b_ih,
                            const float* __restrict__ b_hh,
                            float* __restrict__ out) {
    int i = blockIdx.x * 256 + threadIdx.x;
    int b = i >> 8, ch = i & 255;
    size_t base = (size_t)b * NG;
    float ig = g_part0[base + ch]       + g_part1[base + ch]       + g_part2[base + ch]       + b_ih[ch]       + b_hh[ch];
    float fg = g_part0[base + 256 + ch] + g_part1[base + 256 + ch] + g_part2[base + 256 + ch] + b_ih[256 + ch] + b_hh[256 + ch];
    float gg = g_part0[base + 512 + ch] + g_part1[base + 512 + ch] + g_part2[base + 512 + ch] + b_ih[512 + ch] + b_hh[512 + ch];
    float og = g_part0[base + 768 + ch] + g_part1[base + 768 + ch] + g_part2[base + 768 + ch] + b_ih[768 + ch] + b_hh[768 + ch];
    float cc = sigf(fg) * g_c[i] + sigf(ig) * tanhf(gg);
    float h  = sigf(og) * tanhf(cc);
    g_c[i] = cc;
    g_hf[i] = h;
    out[(size_t)b * (2 * CC) + ch] = h;
    __nv_bfloat16 hi, lo;
    split_bf16(h, hi, lo);
    g_hb_hi[i] = hi;
    g_hb_lo[i] = lo;
}

extern "C" void kernel_launch(void* const* d_in, const int* in_sizes, int n_in,
                              void* d_out, int out_size) {
    const float* x      = (const float*)d_in[0];
    const float* q_star = (const float*)d_in[2];
    const float* bank_s = (const float*)d_in[3];
    const float* w_ih   = (const float*)d_in[4];
    const float* w_hh   = (const float*)d_in[5];
    const float* b_ih   = (const float*)d_in[6];
    const float* b_hh   = (const float*)d_in[7];
    const int*   index  = (const int*)d_in[8];
    float* out = (float*)d_out;

    cudaFuncSetAttribute(f0_kernel, cudaFuncAttributeMaxDynamicSharedMemorySize, GEMM_SMEM);
    cudaFuncSetAttribute(f1_kernel, cudaFuncAttributeMaxDynamicSharedMemorySize, GEMM_SMEM);
    cudaFuncSetAttribute(g_kernel<0>, cudaFuncAttributeMaxDynamicSharedMemorySize, GEMM_SMEM);
    cudaFuncSetAttribute(g_kernel<1>, cudaFuncAttributeMaxDynamicSharedMemorySize, GEMM_SMEM);

    conv_all_kernel<<<(NG * 1280) / 256, 256>>>(w_ih, w_hh);
    qconv_kernel<<<(BB * 512) / 256, 256>>>(q_star);

    // step 1: [q_star-GEMM(K=512)->part0 || asit] ; h0@w_hh(K=256,z2)->part1/2 ; lstm
    f0_kernel<<<NGEMM + BB, 256, GEMM_SMEM>>>(x, bank_s, index);
    g_kernel<0><<<dim3(16, 8, 2), 256, GEMM_SMEM>>>();
    lstm_kernel<<<BB, 256>>>(b_ih, b_hh, out);

    // steps 2..3: [h@Wh(K=256)->part0 || attn] ; r@Wr(K=256,z2)->part1/2 ; lstm
    for (int t = 0; t < 2; t++) {
        f1_kernel<<<NGEMM + BB, 256, GEMM_SMEM>>>(x, out, NGEMM);
        g_kernel<1><<<dim3(16, 8, 2), 256, GEMM_SMEM>>>();
        lstm_kernel<<<BB, 256>>>(b_ih, b_hh, out);
    }

    // final attention (attn blocks only)
    f1_kernel<<<BB, 256, GEMM_SMEM>>>(x, out, 0);
}